// round 9
// baseline (speedup 1.0000x reference)
#include <cuda_runtime.h>
#include <cstdint>

// GCN layer via mma.sync tf32 (HMMA), merged dual-GEMM K-pass.
// BNK=1280, L=64, DIN=512, DOUT=256, NREL=40.
// CTA = 128 rows (2 sentences), 256 threads, 8 warps (2M x 4N, warp 64x64).
// Single K sweep: per chunk load A once + both B tiles, accumulate
// P_in and P_self simultaneously in registers.
// Epilogue: stash P_in to SMEM (within-CTA gather), sigmoid gates (fp32
// GEMVs), relu, mask; P_self stays in registers.

#define BNK_   1280
#define L_     64
#define DIN_   512
#define DOUT_  256
#define MTILE  128
#define KC     32
#define NCHUNK 16

typedef unsigned int u32;

// Pre-transposed, tf32-rounded, SW128-swizzled W: [which][chunk][n=256][k=32]
__device__ float WT_sw[2][NCHUNK][DOUT_][KC];

// ---- SMEM byte offsets ----
#define OFF_GIN 0
#define OFF_GSF 512
#define OFF_A0  1024
#define OFF_A1  (OFF_A0 + 16384)
#define OFF_BI0 (OFF_A1 + 16384)
#define OFF_BI1 (OFF_BI0 + 32768)
#define OFF_BS0 (OFF_BI1 + 32768)
#define OFF_BS1 (OFF_BS0 + 32768)
#define OFF_END (OFF_BS1 + 32768)      // 164864
// Epilogue P_in tile overlays dead stage buffers (starts at OFF_A0)
#define OFF_PIN OFF_A0                  // needs 131072 B -> ends at 132096 < OFF_BS1+...
// Per-row epilogue params live above BS1's start region that PIN doesn't reach
#define OFF_WIN  (OFF_BS1 + 0)
#define OFF_WSF  (OFF_BS1 + 512)
#define OFF_MKV  (OFF_BS1 + 1024)
#define OFF_GLI  (OFF_BS1 + 1536)
#define OFF_LRI  (OFF_BS1 + 2048)
#define SMEM_TOTAL OFF_END

__device__ __forceinline__ u32 smem_u32(const void* p) {
    u32 a;
    asm("{ .reg .u64 t; cvta.to.shared.u64 t, %1; cvt.u32.u64 %0, t; }"
        : "=r"(a) : "l"(p));
    return a;
}
__device__ __forceinline__ void cpa16(u32 dst, const void* src) {
    asm volatile("cp.async.cg.shared.global [%0], [%1], 16;\n"
                 :: "r"(dst), "l"(src));
}

#define MMA8(d, A, B0, B1)                                                    \
    asm volatile(                                                             \
        "mma.sync.aligned.m16n8k8.row.col.f32.tf32.tf32.f32 "                 \
        "{%0,%1,%2,%3}, {%4,%5,%6,%7}, {%8,%9}, {%0,%1,%2,%3};"               \
        : "+f"((d)[0]), "+f"((d)[1]), "+f"((d)[2]), "+f"((d)[3])              \
        : "r"(__float_as_uint((A)[0])), "r"(__float_as_uint((A)[1])),         \
          "r"(__float_as_uint((A)[2])), "r"(__float_as_uint((A)[3])),         \
          "r"(B0), "r"(B1))

#define LDMX4(x0, x1, x2, x3, addr)                                           \
    asm volatile(                                                             \
        "ldmatrix.sync.aligned.m8n8.x4.shared.b16 {%0,%1,%2,%3}, [%4];"       \
        : "=r"(x0), "=r"(x1), "=r"(x2), "=r"(x3) : "r"(addr))

#define CVT_TF32(dst, src)                                                    \
    asm("cvt.rna.tf32.f32 %0, %1;" : "=f"(dst) : "f"(__uint_as_float(src)))

// -------------------- prepass: transpose + tf32-round W ---------------------
extern "C" __global__ void prep_wt(const float* __restrict__ W_in,
                                   const float* __restrict__ W_self)
{
    int idx = blockIdx.x * 256 + threadIdx.x;   // 0 .. 262143
    int which = idx >> 17;
    int rem = idx & 131071;
    int k = rem >> 8;        // 0..511 (coalesced reads over n)
    int n = rem & 255;
    const float* W = which ? W_self : W_in;
    float v = W[k * DOUT_ + n];
    asm("cvt.rna.tf32.f32 %0, %1;" : "=f"(v) : "f"(v));
    int c = k >> 5, kk = k & 31;
    int byte = n * 128 + kk * 4;
    int sw = byte ^ ((byte >> 3) & 0x70);
    *(float*)((char*)&WT_sw[which][c][0][0] + sw) = v;
}

// ------------------------------- main kernel --------------------------------
extern "C" __global__ void __launch_bounds__(256, 1)
gcn_hmma(const float* __restrict__ rep,
         const float* __restrict__ adj_mask_in,
         const float* __restrict__ adj_mask_loop,
         const float* __restrict__ mask,
         const float* __restrict__ b_in,
         const float* __restrict__ bg_in,
         const float* __restrict__ Wg_in,
         const float* __restrict__ Wg_self,
         const int* __restrict__ arc,
         const int* __restrict__ lab,
         float* __restrict__ out)
{
    extern __shared__ char smem[];
    const u32 sb = smem_u32(smem);
    const int tid = threadIdx.x;
    const int ln = tid & 31;
    const int wid = tid >> 5;
    const int wm = wid >> 2;     // 0..1  (M half)
    const int wn = wid & 3;      // 0..3  (N quarter)
    const int g = ln >> 2;
    const int t = ln & 3;
    const int m0 = blockIdx.x * MTILE;

    // ldmatrix lane-address components
    const int rowA = wm * 64 + (ln & 7) + ((ln >> 3) & 1) * 8;   // + mt*16
    const int koffA = ((ln >> 4) & 1) * 16;
    const int rowB = wn * 64 + ((ln >> 4) & 1) * 8 + (ln & 7);   // + nt2*16
    const int koffB = ((ln >> 3) & 1) * 16;

    const u32 sA[2]  = { sb + OFF_A0,  sb + OFF_A1 };
    const u32 sBi[2] = { sb + OFF_BI0, sb + OFF_BI1 };
    const u32 sBs[2] = { sb + OFF_BS0, sb + OFF_BS1 };

    // precomputed cp.async A-destination (swizzled) offsets
    int arow[4], asw[4], aq[4];
#pragma unroll
    for (int i = 0; i < 4; i++) {
        int idx = tid + 256 * i;
        arow[i] = idx >> 3;
        aq[i] = idx & 7;
        int b = arow[i] * 128 + aq[i] * 16;
        asw[i] = b ^ ((b >> 3) & 0x70);
    }

#define LOAD_CHUNK(ch)                                                         \
    do {                                                                       \
        int kc_ = (ch), s_ = (ch) & 1;                                         \
        const char* ab = (const char*)rep + (size_t)m0 * 2048 + kc_ * 128;     \
        _Pragma("unroll")                                                      \
        for (int i = 0; i < 4; i++)                                            \
            cpa16(sA[s_] + asw[i], ab + (size_t)arow[i] * 2048 + aq[i] * 16);  \
        const char* bi = (const char*)WT_sw + (size_t)kc_ * 32768;             \
        const char* bs = bi + (size_t)NCHUNK * 32768;                          \
        _Pragma("unroll")                                                      \
        for (int i = 0; i < 8; i++) {                                          \
            int o = (tid + 256 * i) * 16;                                      \
            cpa16(sBi[s_] + o, bi + o);                                        \
            cpa16(sBs[s_] + o, bs + o);                                        \
        }                                                                      \
        asm volatile("cp.async.commit_group;\n" ::: "memory");                 \
    } while (0)

    // prologue: chunks 0,1
    LOAD_CHUNK(0);
    LOAD_CHUNK(1);

    // ---------------- gate GEMVs (full fp32), overlap prologue --------------
    {
        int row = tid >> 1, half = tid & 1;
        const float4* rp = (const float4*)(rep + (size_t)(m0 + row) * DIN_ + half * 256);
        const float4* gi = (const float4*)(Wg_in + half * 256);
        const float4* gs = (const float4*)(Wg_self + half * 256);
        float ai = 0.f, as = 0.f;
#pragma unroll 8
        for (int q = 0; q < 64; q++) {
            float4 v = rp[q], wi = gi[q], ws = gs[q];
            ai += v.x * wi.x + v.y * wi.y + v.z * wi.z + v.w * wi.w;
            as += v.x * ws.x + v.y * ws.y + v.z * ws.z + v.w * ws.w;
        }
        ai += __shfl_xor_sync(0xffffffffu, ai, 1);
        as += __shfl_xor_sync(0xffffffffu, as, 1);
        if (!half) {
            ((float*)(smem + OFF_GIN))[row] = ai;
            ((float*)(smem + OFF_GSF))[row] = as;
        }
    }

    float acc_in[4][8][4];
    float acc_sf[4][8][4];
#pragma unroll
    for (int mt = 0; mt < 4; mt++)
#pragma unroll
        for (int nt = 0; nt < 8; nt++)
#pragma unroll
            for (int q = 0; q < 4; q++) { acc_in[mt][nt][q] = 0.f; acc_sf[mt][nt][q] = 0.f; }

    // ------------------------------ main loop -------------------------------
#pragma unroll 2
    for (int c = 0; c < NCHUNK; c++) {
        const int s = c & 1;
        if (c == NCHUNK - 1)
            asm volatile("cp.async.wait_group 0;" ::: "memory");
        else
            asm volatile("cp.async.wait_group 1;" ::: "memory");
        __syncthreads();

        const u32 aBase = sA[s], biBase = sBi[s], bsBase = sBs[s];
#pragma unroll
        for (int ks = 0; ks < 4; ks++) {
            float a[4][4];
#pragma unroll
            for (int mt = 0; mt < 4; mt++) {
                int byte = (rowA + mt * 16) * 128 + ks * 32 + koffA;
                byte ^= (byte >> 3) & 0x70;
                u32 x0, x1, x2, x3;
                LDMX4(x0, x1, x2, x3, aBase + byte);
                CVT_TF32(a[mt][0], x0);
                CVT_TF32(a[mt][1], x1);
                CVT_TF32(a[mt][2], x2);
                CVT_TF32(a[mt][3], x3);
            }
#pragma unroll
            for (int nt2 = 0; nt2 < 4; nt2++) {
                int byte = (rowB + nt2 * 16) * 128 + ks * 32 + koffB;
                byte ^= (byte >> 3) & 0x70;
                u32 b0, b1, b2, b3;
                LDMX4(b0, b1, b2, b3, biBase + byte);
                u32 c0, c1, c2, c3;
                LDMX4(c0, c1, c2, c3, bsBase + byte);
#pragma unroll
                for (int mt = 0; mt < 4; mt++) {
                    MMA8(acc_in[mt][2 * nt2],     a[mt], b0, b1);
                    MMA8(acc_sf[mt][2 * nt2],     a[mt], c0, c1);
                    MMA8(acc_in[mt][2 * nt2 + 1], a[mt], b2, b3);
                    MMA8(acc_sf[mt][2 * nt2 + 1], a[mt], c2, c3);
                }
            }
        }
        __syncthreads();  // all warps done with stage s before refill

        if (c < NCHUNK - 2) LOAD_CHUNK(c + 2);
    }

    // ---------------- stash P_in tile to swizzled SMEM -----------------------
#pragma unroll
    for (int mt = 0; mt < 4; mt++)
#pragma unroll
        for (int nt = 0; nt < 8; nt++)
#pragma unroll
            for (int h = 0; h < 2; h++) {
                int r = wm * 64 + mt * 16 + g + h * 8;
                int cc = (wn * 64 + nt * 8 + 2 * t) * 4;
                u32 ad = sb + OFF_PIN + r * 1024 + (cc ^ ((r & 7) << 4));
                asm volatile("st.shared.v2.f32 [%0], {%1,%2};"
                             :: "r"(ad), "f"(acc_in[mt][nt][2 * h]),
                                "f"(acc_in[mt][nt][2 * h + 1]) : "memory");
            }

    // ---------------- per-row epilogue params --------------------------------
    if (tid < MTILE) {
        int r = tid, m = m0 + r;
        int lr = lab[m];
        int gl = (arc[2 * m] * L_ + arc[2 * m + 1]) - m0;
        gl &= (MTILE - 1);
        float mi = adj_mask_in[m], mlp = adj_mask_loop[m];
        float giv = ((float*)(smem + OFF_GIN))[gl] + bg_in[lr];
        float gsv = ((float*)(smem + OFF_GSF))[r];
        ((float*)(smem + OFF_WIN))[r] = (1.f / (1.f + expf(-giv))) * mi * mi;
        ((float*)(smem + OFF_WSF))[r] = (1.f / (1.f + expf(-gsv))) * mlp * mlp;
        ((float*)(smem + OFF_MKV))[r] = mask[m];
        ((int*)(smem + OFF_GLI))[r] = gl;
        ((int*)(smem + OFF_LRI))[r] = lr;
    }
    __syncthreads();

    // ---------------- combine: gather + gates + relu + store -----------------
#pragma unroll
    for (int mt = 0; mt < 4; mt++)
#pragma unroll
        for (int h = 0; h < 2; h++) {
            int r = wm * 64 + mt * 16 + g + h * 8;
            float w_in = ((float*)(smem + OFF_WIN))[r];
            float w_sf = ((float*)(smem + OFF_WSF))[r];
            float mkr = ((float*)(smem + OFF_MKV))[r];
            int gl = ((int*)(smem + OFF_GLI))[r];
            int lr = ((int*)(smem + OFF_LRI))[r];
            const u32 pinrow = sb + OFF_PIN + gl * 1024;
            const int xr = (gl & 7) << 4;
            const float* bb = b_in + lr * DOUT_;
            float* op = out + (size_t)(m0 + r) * DOUT_;
#pragma unroll
            for (int nt = 0; nt < 8; nt++) {
                int cc = wn * 64 + nt * 8 + 2 * t;
                float px, py;
                asm volatile("ld.shared.v2.f32 {%0,%1}, [%2];"
                             : "=f"(px), "=f"(py)
                             : "r"(pinrow + ((cc * 4) ^ xr)));
                float2 bv = *(const float2*)(bb + cc);
                float2 o;
                o.x = fmaxf((px + bv.x) * w_in + acc_sf[mt][nt][2 * h] * w_sf, 0.f) * mkr;
                o.y = fmaxf((py + bv.y) * w_in + acc_sf[mt][nt][2 * h + 1] * w_sf, 0.f) * mkr;
                *(float2*)(op + cc) = o;
            }
        }
}

extern "C" void kernel_launch(void* const* d_in, const int* in_sizes, int n_in,
                              void* d_out, int out_size)
{
    (void)in_sizes; (void)n_in; (void)out_size;
    cudaFuncSetAttribute(gcn_hmma, cudaFuncAttributeMaxDynamicSharedMemorySize,
                         SMEM_TOTAL);
    prep_wt<<<1024, 256>>>((const float*)d_in[4], (const float*)d_in[8]);
    gcn_hmma<<<BNK_ / 2, 256, SMEM_TOTAL>>>(
        (const float*)d_in[0],   // rep
        (const float*)d_in[1],   // adj_mask_in
        (const float*)d_in[2],   // adj_mask_loop
        (const float*)d_in[3],   // mask
        (const float*)d_in[5],   // b_in
        (const float*)d_in[7],   // b_gate_in
        (const float*)d_in[6],   // W_gate_in
        (const float*)d_in[9],   // W_gate_self
        (const int*)d_in[10],    // adj_arc_in
        (const int*)d_in[11],    // adj_lab_in
        (float*)d_out);
}

// round 10
// speedup vs baseline: 1.9710x; 1.9710x over previous
#include <cuda_runtime.h>
#include <cstdint>

// GCN layer via mma.sync tf32 (HMMA), merged dual-GEMM, N-split CTAs.
// BNK=1280, L=64, DIN=512, DOUT=256, NREL=40.
// CTA = 1 sentence (64 rows) x 128 output cols; 2560 CTAs; 256 threads,
// 8 warps (2M x 4N, warp 32x32 per GEMM, dual accumulators = 64 regs).
// Single K sweep accumulates P_in and P_self together; P_in stashed to SMEM
// after mainloop for within-sentence row gather; 2 CTAs/SM via <=128 regs.

#define BNK_   1280
#define L_     64
#define DIN_   512
#define DOUT_  256
#define KC     32
#define NCHUNK 16

typedef unsigned int u32;

// Pre-transposed, tf32-rounded, SW128-swizzled W: [which][chunk][n=256][k=32]
__device__ float WT_sw[2][NCHUNK][DOUT_][KC];

// ---- SMEM byte offsets ----
#define OFF_GIN  0
#define OFF_GSF  256
#define OFF_WIN  512
#define OFF_WSF  768
#define OFF_MKV  1024
#define OFF_GLI  1280
#define OFF_LRI  1536
#define OFF_A0   2048
#define OFF_A1   (OFF_A0 + 8192)
#define OFF_BI0  (OFF_A1 + 8192)
#define OFF_BI1  (OFF_BI0 + 16384)
#define OFF_BS0  (OFF_BI1 + 16384)
#define OFF_BS1  (OFF_BS0 + 16384)
#define SMEM_TOTAL (OFF_BS1 + 16384)   // 83968 B -> 2 CTAs/SM
// P_in tile (64 x 128 x 4 = 32768 B) overlays dead stage buffers post-mainloop
#define OFF_PIN  OFF_A0

__device__ __forceinline__ u32 smem_u32(const void* p) {
    u32 a;
    asm("{ .reg .u64 t; cvta.to.shared.u64 t, %1; cvt.u32.u64 %0, t; }"
        : "=r"(a) : "l"(p));
    return a;
}
__device__ __forceinline__ void cpa16(u32 dst, const void* src) {
    asm volatile("cp.async.cg.shared.global [%0], [%1], 16;\n"
                 :: "r"(dst), "l"(src));
}

#define MMA8(d, A, B0, B1)                                                    \
    asm volatile(                                                             \
        "mma.sync.aligned.m16n8k8.row.col.f32.tf32.tf32.f32 "                 \
        "{%0,%1,%2,%3}, {%4,%5,%6,%7}, {%8,%9}, {%0,%1,%2,%3};"               \
        : "+f"((d)[0]), "+f"((d)[1]), "+f"((d)[2]), "+f"((d)[3])              \
        : "r"(__float_as_uint((A)[0])), "r"(__float_as_uint((A)[1])),         \
          "r"(__float_as_uint((A)[2])), "r"(__float_as_uint((A)[3])),         \
          "r"(B0), "r"(B1))

#define LDMX4(x0, x1, x2, x3, addr)                                           \
    asm volatile(                                                             \
        "ldmatrix.sync.aligned.m8n8.x4.shared.b16 {%0,%1,%2,%3}, [%4];"       \
        : "=r"(x0), "=r"(x1), "=r"(x2), "=r"(x3) : "r"(addr))

#define CVT_TF32(dst, src)                                                    \
    asm("cvt.rna.tf32.f32 %0, %1;" : "=f"(dst) : "f"(__uint_as_float(src)))

// -------------------- prepass: transpose + tf32-round W ---------------------
extern "C" __global__ void prep_wt(const float* __restrict__ W_in,
                                   const float* __restrict__ W_self)
{
    int idx = blockIdx.x * 256 + threadIdx.x;   // 0 .. 262143
    int which = idx >> 17;
    int rem = idx & 131071;
    int k = rem >> 8;        // 0..511 (coalesced reads over n)
    int n = rem & 255;
    const float* W = which ? W_self : W_in;
    float v = W[k * DOUT_ + n];
    asm("cvt.rna.tf32.f32 %0, %1;" : "=f"(v) : "f"(v));
    int c = k >> 5, kk = k & 31;
    int byte = n * 128 + kk * 4;
    int sw = byte ^ ((byte >> 3) & 0x70);
    *(float*)((char*)&WT_sw[which][c][0][0] + sw) = v;
}

// ------------------------------- main kernel --------------------------------
extern "C" __global__ void __launch_bounds__(256, 2)
gcn_hmma(const float* __restrict__ rep,
         const float* __restrict__ adj_mask_in,
         const float* __restrict__ adj_mask_loop,
         const float* __restrict__ mask,
         const float* __restrict__ b_in,
         const float* __restrict__ bg_in,
         const float* __restrict__ Wg_in,
         const float* __restrict__ Wg_self,
         const int* __restrict__ arc,
         const int* __restrict__ lab,
         float* __restrict__ out)
{
    extern __shared__ char smem[];
    const u32 sb = smem_u32(smem);
    const int tid = threadIdx.x;
    const int ln = tid & 31;
    const int wid = tid >> 5;
    const int wm = wid >> 2;     // 0..1  (M half: 32 rows)
    const int wn = wid & 3;      // 0..3  (N quarter: 32 cols)
    const int g = ln >> 2;
    const int t = ln & 3;
    const int sent = blockIdx.x >> 1;
    const int nh = blockIdx.x & 1;       // which 128-col half
    const int m0 = sent * L_;
    const int c0 = nh * 128;

    // ldmatrix lane-address components
    const int rowA = wm * 32 + (ln & 7) + ((ln >> 3) & 1) * 8;   // + mt*16
    const int koffA = ((ln >> 4) & 1) * 16;
    const int rowB = wn * 32 + ((ln >> 4) & 1) * 8 + (ln & 7);   // + nt2*16
    const int koffB = ((ln >> 3) & 1) * 16;

    const u32 sA[2]  = { sb + OFF_A0,  sb + OFF_A1 };
    const u32 sBi[2] = { sb + OFF_BI0, sb + OFF_BI1 };
    const u32 sBs[2] = { sb + OFF_BS0, sb + OFF_BS1 };

    // precomputed cp.async A-destination (swizzled) offsets: 512 float4 total
    int arow[2], asw[2], aq[2];
#pragma unroll
    for (int i = 0; i < 2; i++) {
        int idx = tid + 256 * i;
        arow[i] = idx >> 3;
        aq[i] = idx & 7;
        int b = arow[i] * 128 + aq[i] * 16;
        asw[i] = b ^ ((b >> 3) & 0x70);
    }

#define LOAD_CHUNK(ch)                                                         \
    do {                                                                       \
        int kc_ = (ch), s_ = (ch) & 1;                                         \
        const char* ab = (const char*)rep + (size_t)m0 * 2048 + kc_ * 128;     \
        _Pragma("unroll")                                                      \
        for (int i = 0; i < 2; i++)                                            \
            cpa16(sA[s_] + asw[i], ab + (size_t)arow[i] * 2048 + aq[i] * 16);  \
        const char* bi = (const char*)WT_sw                                    \
                       + ((size_t)kc_ * 256 + nh * 128) * 128;                 \
        const char* bs = bi + (size_t)NCHUNK * 32768;                          \
        _Pragma("unroll")                                                      \
        for (int i = 0; i < 4; i++) {                                          \
            int o = (tid + 256 * i) * 16;                                      \
            cpa16(sBi[s_] + o, bi + o);                                        \
            cpa16(sBs[s_] + o, bs + o);                                        \
        }                                                                      \
        asm volatile("cp.async.commit_group;\n" ::: "memory");                 \
    } while (0)

    // prologue: chunks 0,1
    LOAD_CHUNK(0);
    LOAD_CHUNK(1);

    // ---------------- gate GEMVs (full fp32), overlap prologue --------------
    {
        int row = tid >> 2, part = tid & 3;   // 64 rows x 4 K-quarters
        const float4* rp = (const float4*)(rep + (size_t)(m0 + row) * DIN_ + part * 128);
        const float4* gi = (const float4*)(Wg_in + part * 128);
        const float4* gs = (const float4*)(Wg_self + part * 128);
        float ai = 0.f, as = 0.f;
#pragma unroll 8
        for (int q = 0; q < 32; q++) {
            float4 v = rp[q], wi = gi[q], ws = gs[q];
            ai += v.x * wi.x + v.y * wi.y + v.z * wi.z + v.w * wi.w;
            as += v.x * ws.x + v.y * ws.y + v.z * ws.z + v.w * ws.w;
        }
        ai += __shfl_xor_sync(0xffffffffu, ai, 1);
        ai += __shfl_xor_sync(0xffffffffu, ai, 2);
        as += __shfl_xor_sync(0xffffffffu, as, 1);
        as += __shfl_xor_sync(0xffffffffu, as, 2);
        if (part == 0) {
            ((float*)(smem + OFF_GIN))[row] = ai;
            ((float*)(smem + OFF_GSF))[row] = as;
        }
    }

    float acc_in[2][4][4];
    float acc_sf[2][4][4];
#pragma unroll
    for (int mt = 0; mt < 2; mt++)
#pragma unroll
        for (int nt = 0; nt < 4; nt++)
#pragma unroll
            for (int q = 0; q < 4; q++) { acc_in[mt][nt][q] = 0.f; acc_sf[mt][nt][q] = 0.f; }

    // ------------------------------ main loop -------------------------------
#pragma unroll 1
    for (int c = 0; c < NCHUNK; c++) {
        const int s = c & 1;
        if (c == NCHUNK - 1)
            asm volatile("cp.async.wait_group 0;" ::: "memory");
        else
            asm volatile("cp.async.wait_group 1;" ::: "memory");
        __syncthreads();

        const u32 aBase = sA[s], biBase = sBi[s], bsBase = sBs[s];
#pragma unroll
        for (int ks = 0; ks < 4; ks++) {
            float a[2][4];
#pragma unroll
            for (int mt = 0; mt < 2; mt++) {
                int byte = (rowA + mt * 16) * 128 + ks * 32 + koffA;
                byte ^= (byte >> 3) & 0x70;
                u32 x0, x1, x2, x3;
                LDMX4(x0, x1, x2, x3, aBase + byte);
                CVT_TF32(a[mt][0], x0);
                CVT_TF32(a[mt][1], x1);
                CVT_TF32(a[mt][2], x2);
                CVT_TF32(a[mt][3], x3);
            }
#pragma unroll
            for (int nt2 = 0; nt2 < 2; nt2++) {
                int byte = (rowB + nt2 * 16) * 128 + ks * 32 + koffB;
                byte ^= (byte >> 3) & 0x70;
                u32 b0, b1, b2, b3;
                LDMX4(b0, b1, b2, b3, biBase + byte);
                u32 e0, e1, e2, e3;
                LDMX4(e0, e1, e2, e3, bsBase + byte);
#pragma unroll
                for (int mt = 0; mt < 2; mt++) {
                    MMA8(acc_in[mt][2 * nt2],     a[mt], b0, b1);
                    MMA8(acc_sf[mt][2 * nt2],     a[mt], e0, e1);
                    MMA8(acc_in[mt][2 * nt2 + 1], a[mt], b2, b3);
                    MMA8(acc_sf[mt][2 * nt2 + 1], a[mt], e2, e3);
                }
            }
        }
        __syncthreads();  // all warps done with stage s before refill

        if (c < NCHUNK - 2) LOAD_CHUNK(c + 2);
    }

    __syncthreads();  // mainloop fully done: stage buffers dead -> PIN overlay

    // ---------------- stash P_in tile (64 x 128) to swizzled SMEM -----------
#pragma unroll
    for (int mt = 0; mt < 2; mt++)
#pragma unroll
        for (int nt = 0; nt < 4; nt++)
#pragma unroll
            for (int h = 0; h < 2; h++) {
                int r = wm * 32 + mt * 16 + g + h * 8;
                int cc4 = (wn * 32 + nt * 8 + 2 * t) * 4;
                u32 ad = sb + OFF_PIN + r * 512 + (cc4 ^ ((r & 7) << 4));
                asm volatile("st.shared.v2.f32 [%0], {%1,%2};"
                             :: "r"(ad), "f"(acc_in[mt][nt][2 * h]),
                                "f"(acc_in[mt][nt][2 * h + 1]) : "memory");
            }

    // ---------------- per-row epilogue params -------------------------------
    if (tid < L_) {
        int r = tid, m = m0 + r;
        int lr = lab[m];
        int gl = (arc[2 * m] * L_ + arc[2 * m + 1]) - m0;
        gl &= (L_ - 1);
        float mi = adj_mask_in[m], mlp = adj_mask_loop[m];
        float giv = ((float*)(smem + OFF_GIN))[gl] + bg_in[lr];
        float gsv = ((float*)(smem + OFF_GSF))[r];
        ((float*)(smem + OFF_WIN))[r] = (1.f / (1.f + expf(-giv))) * mi * mi;
        ((float*)(smem + OFF_WSF))[r] = (1.f / (1.f + expf(-gsv))) * mlp * mlp;
        ((float*)(smem + OFF_MKV))[r] = mask[m];
        ((int*)(smem + OFF_GLI))[r] = gl;
        ((int*)(smem + OFF_LRI))[r] = lr;
    }
    __syncthreads();

    // ---------------- combine: gather + gates + relu + store ----------------
#pragma unroll
    for (int mt = 0; mt < 2; mt++)
#pragma unroll
        for (int h = 0; h < 2; h++) {
            int r = wm * 32 + mt * 16 + g + h * 8;
            float w_in = ((float*)(smem + OFF_WIN))[r];
            float w_sf = ((float*)(smem + OFF_WSF))[r];
            float mkr = ((float*)(smem + OFF_MKV))[r];
            int gl = ((int*)(smem + OFF_GLI))[r];
            int lr = ((int*)(smem + OFF_LRI))[r];
            const u32 pinrow = sb + OFF_PIN + gl * 512;
            const int xr = (gl & 7) << 4;
            const float* bb = b_in + lr * DOUT_ + c0;
            float* op = out + (size_t)(m0 + r) * DOUT_ + c0;
#pragma unroll
            for (int nt = 0; nt < 4; nt++) {
                int cc = wn * 32 + nt * 8 + 2 * t;
                float px, py;
                asm volatile("ld.shared.v2.f32 {%0,%1}, [%2];"
                             : "=f"(px), "=f"(py)
                             : "r"(pinrow + ((cc * 4) ^ xr)));
                float2 bv = *(const float2*)(bb + cc);
                float2 o;
                o.x = fmaxf((px + bv.x) * w_in + acc_sf[mt][nt][2 * h] * w_sf, 0.f) * mkr;
                o.y = fmaxf((py + bv.y) * w_in + acc_sf[mt][nt][2 * h + 1] * w_sf, 0.f) * mkr;
                *(float2*)(op + cc) = o;
            }
        }
}

extern "C" void kernel_launch(void* const* d_in, const int* in_sizes, int n_in,
                              void* d_out, int out_size)
{
    (void)in_sizes; (void)n_in; (void)out_size;
    cudaFuncSetAttribute(gcn_hmma, cudaFuncAttributeMaxDynamicSharedMemorySize,
                         SMEM_TOTAL);
    prep_wt<<<1024, 256>>>((const float*)d_in[4], (const float*)d_in[8]);
    gcn_hmma<<<BNK_ * 2, 256, SMEM_TOTAL>>>(
        (const float*)d_in[0],   // rep
        (const float*)d_in[1],   // adj_mask_in
        (const float*)d_in[2],   // adj_mask_loop
        (const float*)d_in[3],   // mask
        (const float*)d_in[5],   // b_in
        (const float*)d_in[7],   // b_gate_in
        (const float*)d_in[6],   // W_gate_in
        (const float*)d_in[9],   // W_gate_self
        (const int*)d_in[10],    // adj_arc_in
        (const int*)d_in[11],    // adj_lab_in
        (float*)d_out);
}

// round 11
// speedup vs baseline: 1.9845x; 1.0069x over previous
#include <cuda_runtime.h>
#include <cstdint>

// GCN layer via mma.sync tf32 (HMMA), merged dual-GEMM, N-split CTAs.
// BNK=1280, L=64, DIN=512, DOUT=256, NREL=40.
// CTA = 1 sentence (64 rows) x 128 output cols; 2560 CTAs; 256 threads,
// 8 warps (2M x 4N), warp 32x32 per GEMM, dual accumulators (64 regs).
// B_in:   cp.async -> SMEM -> ldmatrix (L1 pipe)
// B_self: fragment-order global buffer -> LDG.128 direct to regs (L2 pipe)
// One barrier per chunk (load c+1 at top, compute c, wait, sync).

#define BNK_   1280
#define L_     64
#define DIN_   512
#define DOUT_  256
#define KC     32
#define NCHUNK 16

typedef unsigned int u32;

// W_in: pre-transposed, tf32-rounded, SW128-swizzled: [chunk][n=256][k=32]
__device__ float WT_in[NCHUNK][DOUT_][KC];
// W_self: tf32-rounded, per-lane fragment order:
//   float4 index f4 = ((c*16 + j)*4 + ks)*32 + lane,  j = global n16 group
//   comp0 = B[k0+(l&3)][n16j*16+(l>>2)], comp1 = +k4, comp2/3 = n+8 same ks
__device__ float4 BF_self[NCHUNK * 16 * 4 * 32];

// ---- SMEM byte offsets ----
#define OFF_GIN  0
#define OFF_GSF  256
#define OFF_WIN  512
#define OFF_WSF  768
#define OFF_MKV  1024
#define OFF_GLI  1280
#define OFF_LRI  1536
#define OFF_A0   2048
#define OFF_A1   (OFF_A0 + 8192)
#define OFF_BI0  (OFF_A1 + 8192)
#define OFF_BI1  (OFF_BI0 + 16384)
#define SMEM_TOTAL (OFF_BI1 + 16384)   // 51200 B
// P_in tile (64 x 128 x 4 = 32768 B) overlays dead stage buffers post-mainloop
#define OFF_PIN  OFF_A0

__device__ __forceinline__ u32 smem_u32(const void* p) {
    u32 a;
    asm("{ .reg .u64 t; cvta.to.shared.u64 t, %1; cvt.u32.u64 %0, t; }"
        : "=r"(a) : "l"(p));
    return a;
}
__device__ __forceinline__ void cpa16(u32 dst, const void* src) {
    asm volatile("cp.async.cg.shared.global [%0], [%1], 16;\n"
                 :: "r"(dst), "l"(src));
}

#define MMA8(d, A, B0, B1)                                                    \
    asm volatile(                                                             \
        "mma.sync.aligned.m16n8k8.row.col.f32.tf32.tf32.f32 "                 \
        "{%0,%1,%2,%3}, {%4,%5,%6,%7}, {%8,%9}, {%0,%1,%2,%3};"               \
        : "+f"((d)[0]), "+f"((d)[1]), "+f"((d)[2]), "+f"((d)[3])              \
        : "r"(__float_as_uint((A)[0])), "r"(__float_as_uint((A)[1])),         \
          "r"(__float_as_uint((A)[2])), "r"(__float_as_uint((A)[3])),         \
          "r"(B0), "r"(B1))

#define LDMX4(x0, x1, x2, x3, addr)                                           \
    asm volatile(                                                             \
        "ldmatrix.sync.aligned.m8n8.x4.shared.b16 {%0,%1,%2,%3}, [%4];"       \
        : "=r"(x0), "=r"(x1), "=r"(x2), "=r"(x3) : "r"(addr))

#define CVT_TF32(dst, src)                                                    \
    asm("cvt.rna.tf32.f32 %0, %1;" : "=f"(dst) : "f"(__uint_as_float(src)))

// -------------------- prepass: round/transpose/arrange W --------------------
extern "C" __global__ void prep_wt(const float* __restrict__ W_in,
                                   const float* __restrict__ W_self)
{
    int idx = blockIdx.x * 256 + threadIdx.x;   // 0 .. 262143
    int which = idx >> 17;
    int rem = idx & 131071;
    if (!which) {
        // W_in -> SW128-swizzled [chunk][n][k] image
        int k = rem >> 8, n = rem & 255;
        float v = W_in[k * DOUT_ + n];
        asm("cvt.rna.tf32.f32 %0, %1;" : "=f"(v) : "f"(v));
        int c = k >> 5, kk = k & 31;
        int byte = n * 128 + kk * 4;
        int sw = byte ^ ((byte >> 3) & 0x70);
        *(float*)((char*)WT_in + (size_t)c * 32768 + sw) = v;
    } else {
        // W_self -> per-lane fragment order
        int f4 = rem >> 2, comp = rem & 3;
        int c = f4 >> 11;
        int r1 = f4 & 2047;
        int j = r1 >> 7;
        int r2 = r1 & 127;
        int ks = r2 >> 5;
        int l = r2 & 31;
        int n = j * 16 + ((comp >> 1) << 3) + (l >> 2);
        int k = c * 32 + ks * 8 + ((comp & 1) << 2) + (l & 3);
        float v = W_self[k * DOUT_ + n];
        asm("cvt.rna.tf32.f32 %0, %1;" : "=f"(v) : "f"(v));
        ((float*)BF_self)[rem] = v;
    }
}

// ------------------------------- main kernel --------------------------------
extern "C" __global__ void __launch_bounds__(256, 2)
gcn_hmma(const float* __restrict__ rep,
         const float* __restrict__ adj_mask_in,
         const float* __restrict__ adj_mask_loop,
         const float* __restrict__ mask,
         const float* __restrict__ b_in,
         const float* __restrict__ bg_in,
         const float* __restrict__ Wg_in,
         const float* __restrict__ Wg_self,
         const int* __restrict__ arc,
         const int* __restrict__ lab,
         float* __restrict__ out)
{
    extern __shared__ char smem[];
    const u32 sb = smem_u32(smem);
    const int tid = threadIdx.x;
    const int ln = tid & 31;
    const int wid = tid >> 5;
    const int wm = wid >> 2;     // 0..1  (M half: 32 rows)
    const int wn = wid & 3;      // 0..3  (N quarter: 32 cols)
    const int g = ln >> 2;
    const int t = ln & 3;
    const int sent = blockIdx.x >> 1;
    const int nh = blockIdx.x & 1;       // which 128-col half
    const int m0 = sent * L_;
    const int c0 = nh * 128;
    const int j0 = nh * 8 + wn * 2;      // global n16 group base for this warp

    // ldmatrix lane-address components
    const int rowA = wm * 32 + (ln & 7) + ((ln >> 3) & 1) * 8;   // + mt*16
    const int koffA = ((ln >> 4) & 1) * 16;
    const int rowB = wn * 32 + ((ln >> 4) & 1) * 8 + (ln & 7);   // + nt2*16
    const int koffB = ((ln >> 3) & 1) * 16;

    const u32 sA[2]  = { sb + OFF_A0,  sb + OFF_A1 };
    const u32 sBi[2] = { sb + OFF_BI0, sb + OFF_BI1 };

    // precomputed cp.async A-destination (swizzled) offsets: 512 float4 total
    int arow[2], asw[2], aq[2];
#pragma unroll
    for (int i = 0; i < 2; i++) {
        int idx = tid + 256 * i;
        arow[i] = idx >> 3;
        aq[i] = idx & 7;
        int b = arow[i] * 128 + aq[i] * 16;
        asw[i] = b ^ ((b >> 3) & 0x70);
    }

#define LOAD_CHUNK(ch)                                                         \
    do {                                                                       \
        int kc_ = (ch), s_ = (ch) & 1;                                         \
        const char* ab = (const char*)rep + (size_t)m0 * 2048 + kc_ * 128;     \
        _Pragma("unroll")                                                      \
        for (int i = 0; i < 2; i++)                                            \
            cpa16(sA[s_] + asw[i], ab + (size_t)arow[i] * 2048 + aq[i] * 16);  \
        const char* bi = (const char*)WT_in + (size_t)kc_ * 32768 + nh * 16384;\
        _Pragma("unroll")                                                      \
        for (int i = 0; i < 4; i++) {                                          \
            int o = (tid + 256 * i) * 16;                                      \
            cpa16(sBi[s_] + o, bi + o);                                        \
        }                                                                      \
        asm volatile("cp.async.commit_group;\n" ::: "memory");                 \
    } while (0)

    // prologue: chunk 0
    LOAD_CHUNK(0);

    // ---------------- gate GEMVs (full fp32), overlap prologue --------------
    {
        int row = tid >> 2, part = tid & 3;   // 64 rows x 4 K-quarters
        const float4* rp = (const float4*)(rep + (size_t)(m0 + row) * DIN_ + part * 128);
        const float4* gi = (const float4*)(Wg_in + part * 128);
        const float4* gs = (const float4*)(Wg_self + part * 128);
        float ai = 0.f, as = 0.f;
#pragma unroll 8
        for (int q = 0; q < 32; q++) {
            float4 v = rp[q], wi = gi[q], ws = gs[q];
            ai += v.x * wi.x + v.y * wi.y + v.z * wi.z + v.w * wi.w;
            as += v.x * ws.x + v.y * ws.y + v.z * ws.z + v.w * ws.w;
        }
        ai += __shfl_xor_sync(0xffffffffu, ai, 1);
        ai += __shfl_xor_sync(0xffffffffu, ai, 2);
        as += __shfl_xor_sync(0xffffffffu, as, 1);
        as += __shfl_xor_sync(0xffffffffu, as, 2);
        if (part == 0) {
            ((float*)(smem + OFF_GIN))[row] = ai;
            ((float*)(smem + OFF_GSF))[row] = as;
        }
    }

    float acc_in[2][4][4];
    float acc_sf[2][4][4];
#pragma unroll
    for (int mt = 0; mt < 2; mt++)
#pragma unroll
        for (int nt = 0; nt < 4; nt++)
#pragma unroll
            for (int q = 0; q < 4; q++) { acc_in[mt][nt][q] = 0.f; acc_sf[mt][nt][q] = 0.f; }

    asm volatile("cp.async.wait_group 0;" ::: "memory");
    __syncthreads();

    // ------------------------------ main loop -------------------------------
    // One barrier per chunk: issue loads for c+1, compute c, wait, sync.
#pragma unroll 1
    for (int c = 0; c < NCHUNK; c++) {
        const int s = c & 1;
        if (c < NCHUNK - 1) LOAD_CHUNK(c + 1);

        const u32 aBase = sA[s], biBase = sBi[s];
        const float4* bfc = BF_self + (size_t)(c * 16 + j0) * 128;
#pragma unroll
        for (int ks = 0; ks < 4; ks++) {
            float a[2][4];
#pragma unroll
            for (int mt = 0; mt < 2; mt++) {
                int byte = (rowA + mt * 16) * 128 + ks * 32 + koffA;
                byte ^= (byte >> 3) & 0x70;
                u32 x0, x1, x2, x3;
                LDMX4(x0, x1, x2, x3, aBase + byte);
                CVT_TF32(a[mt][0], x0);
                CVT_TF32(a[mt][1], x1);
                CVT_TF32(a[mt][2], x2);
                CVT_TF32(a[mt][3], x3);
            }
#pragma unroll
            for (int nt2 = 0; nt2 < 2; nt2++) {
                // B_self fragments: one LDG.128 from L2-resident buffer
                float4 e = __ldg(bfc + nt2 * 128 + ks * 32 + ln);
                u32 e0 = __float_as_uint(e.x), e1 = __float_as_uint(e.y);
                u32 e2 = __float_as_uint(e.z), e3 = __float_as_uint(e.w);
                // B_in fragments: ldmatrix from SMEM stage
                int byte = (rowB + nt2 * 16) * 128 + ks * 32 + koffB;
                byte ^= (byte >> 3) & 0x70;
                u32 b0, b1, b2, b3;
                LDMX4(b0, b1, b2, b3, biBase + byte);
#pragma unroll
                for (int mt = 0; mt < 2; mt++) {
                    MMA8(acc_in[mt][2 * nt2],     a[mt], b0, b1);
                    MMA8(acc_sf[mt][2 * nt2],     a[mt], e0, e1);
                    MMA8(acc_in[mt][2 * nt2 + 1], a[mt], b2, b3);
                    MMA8(acc_sf[mt][2 * nt2 + 1], a[mt], e2, e3);
                }
            }
        }

        if (c < NCHUNK - 1)
            asm volatile("cp.async.wait_group 0;" ::: "memory");
        __syncthreads();
    }

    // ---------------- stash P_in tile (64 x 128) to swizzled SMEM -----------
#pragma unroll
    for (int mt = 0; mt < 2; mt++)
#pragma unroll
        for (int nt = 0; nt < 4; nt++)
#pragma unroll
            for (int h = 0; h < 2; h++) {
                int r = wm * 32 + mt * 16 + g + h * 8;
                int cc4 = (wn * 32 + nt * 8 + 2 * t) * 4;
                u32 ad = sb + OFF_PIN + r * 512 + (cc4 ^ ((r & 7) << 4));
                asm volatile("st.shared.v2.f32 [%0], {%1,%2};"
                             :: "r"(ad), "f"(acc_in[mt][nt][2 * h]),
                                "f"(acc_in[mt][nt][2 * h + 1]) : "memory");
            }

    // ---------------- per-row epilogue params -------------------------------
    if (tid < L_) {
        int r = tid, m = m0 + r;
        int lr = lab[m];
        int gl = (arc[2 * m] * L_ + arc[2 * m + 1]) - m0;
        gl &= (L_ - 1);
        float mi = adj_mask_in[m], mlp = adj_mask_loop[m];
        float giv = ((float*)(smem + OFF_GIN))[gl] + bg_in[lr];
        float gsv = ((float*)(smem + OFF_GSF))[r];
        ((float*)(smem + OFF_WIN))[r] = (1.f / (1.f + expf(-giv))) * mi * mi;
        ((float*)(smem + OFF_WSF))[r] = (1.f / (1.f + expf(-gsv))) * mlp * mlp;
        ((float*)(smem + OFF_MKV))[r] = mask[m];
        ((int*)(smem + OFF_GLI))[r] = gl;
        ((int*)(smem + OFF_LRI))[r] = lr;
    }
    __syncthreads();

    // ---------------- combine: gather + gates + relu + store ----------------
#pragma unroll
    for (int mt = 0; mt < 2; mt++)
#pragma unroll
        for (int h = 0; h < 2; h++) {
            int r = wm * 32 + mt * 16 + g + h * 8;
            float w_in = ((float*)(smem + OFF_WIN))[r];
            float w_sf = ((float*)(smem + OFF_WSF))[r];
            float mkr = ((float*)(smem + OFF_MKV))[r];
            int gl = ((int*)(smem + OFF_GLI))[r];
            int lr = ((int*)(smem + OFF_LRI))[r];
            const u32 pinrow = sb + OFF_PIN + gl * 512;
            const int xr = (gl & 7) << 4;
            const float* bb = b_in + lr * DOUT_ + c0;
            float* op = out + (size_t)(m0 + r) * DOUT_ + c0;
#pragma unroll
            for (int nt = 0; nt < 4; nt++) {
                int cc = wn * 32 + nt * 8 + 2 * t;
                float px, py;
                asm volatile("ld.shared.v2.f32 {%0,%1}, [%2];"
                             : "=f"(px), "=f"(py)
                             : "r"(pinrow + ((cc * 4) ^ xr)));
                float2 bv = *(const float2*)(bb + cc);
                float2 o;
                o.x = fmaxf((px + bv.x) * w_in + acc_sf[mt][nt][2 * h] * w_sf, 0.f) * mkr;
                o.y = fmaxf((py + bv.y) * w_in + acc_sf[mt][nt][2 * h + 1] * w_sf, 0.f) * mkr;
                *(float2*)(op + cc) = o;
            }
        }
}

extern "C" void kernel_launch(void* const* d_in, const int* in_sizes, int n_in,
                              void* d_out, int out_size)
{
    (void)in_sizes; (void)n_in; (void)out_size;
    cudaFuncSetAttribute(gcn_hmma, cudaFuncAttributeMaxDynamicSharedMemorySize,
                         SMEM_TOTAL);
    prep_wt<<<1024, 256>>>((const float*)d_in[4], (const float*)d_in[8]);
    gcn_hmma<<<BNK_ * 2, 256, SMEM_TOTAL>>>(
        (const float*)d_in[0],   // rep
        (const float*)d_in[1],   // adj_mask_in
        (const float*)d_in[2],   // adj_mask_loop
        (const float*)d_in[3],   // mask
        (const float*)d_in[5],   // b_in
        (const float*)d_in[7],   // b_gate_in
        (const float*)d_in[6],   // W_gate_in
        (const float*)d_in[9],   // W_gate_self
        (const int*)d_in[10],    // adj_arc_in
        (const int*)d_in[11],    // adj_lab_in
        (float*)d_out);
}

// round 12
// speedup vs baseline: 2.1023x; 1.0594x over previous
#include <cuda_runtime.h>
#include <cstdint>

// GCN layer via mma.sync tf32 (HMMA): N-half phases, merged dual-GEMM,
// 3-stage cp.async pipeline, one barrier per chunk.
// BNK=1280, L=64, DIN=512, DOUT=256, NREL=40.
// CTA = 128 rows (2 sentences), 256 threads, 8 warps (2M x 4N).
// Phase p (cols p*128..p*128+127): warp tile 64x32 DUAL (P_in + P_self),
// acc = 128 regs. Epilogue per phase: stash P_in half to SMEM, gather
// within CTA, sigmoid gates (fp32 GEMVs), relu, mask, store.

#define BNK_   1280
#define L_     64
#define DIN_   512
#define DOUT_  256
#define KC     32
#define NCHUNK 16

typedef unsigned int u32;

// Pre-transposed, tf32-rounded, SW128-swizzled W: [which][chunk][n=256][k=32]
__device__ float WT_sw[2][NCHUNK][DOUT_][KC];

// ---- SMEM byte offsets ----
#define OFF_GIN  0
#define OFF_GSF  512
#define OFF_WIN  1024
#define OFF_WSF  1536
#define OFF_MKV  2048
#define OFF_GLI  2560
#define OFF_LRI  3072
#define OFF_STG  4096
#define STG_STRIDE 49152          // A 16K + Bi 16K + Bs 16K
#define OFF_PIN  (OFF_STG + 3 * STG_STRIDE)    // 151552
#define SMEM_TOTAL (OFF_PIN + 65536)           // 217088

__device__ __forceinline__ u32 smem_u32(const void* p) {
    u32 a;
    asm("{ .reg .u64 t; cvta.to.shared.u64 t, %1; cvt.u32.u64 %0, t; }"
        : "=r"(a) : "l"(p));
    return a;
}
__device__ __forceinline__ void cpa16(u32 dst, const void* src) {
    asm volatile("cp.async.cg.shared.global [%0], [%1], 16;\n"
                 :: "r"(dst), "l"(src));
}

#define MMA8(d, A, B0, B1)                                                    \
    asm volatile(                                                             \
        "mma.sync.aligned.m16n8k8.row.col.f32.tf32.tf32.f32 "                 \
        "{%0,%1,%2,%3}, {%4,%5,%6,%7}, {%8,%9}, {%0,%1,%2,%3};"               \
        : "+f"((d)[0]), "+f"((d)[1]), "+f"((d)[2]), "+f"((d)[3])              \
        : "r"(__float_as_uint((A)[0])), "r"(__float_as_uint((A)[1])),         \
          "r"(__float_as_uint((A)[2])), "r"(__float_as_uint((A)[3])),         \
          "r"(B0), "r"(B1))

#define LDMX4(x0, x1, x2, x3, addr)                                           \
    asm volatile(                                                             \
        "ldmatrix.sync.aligned.m8n8.x4.shared.b16 {%0,%1,%2,%3}, [%4];"       \
        : "=r"(x0), "=r"(x1), "=r"(x2), "=r"(x3) : "r"(addr))

#define CVT_TF32(dst, src)                                                    \
    asm("cvt.rna.tf32.f32 %0, %1;" : "=f"(dst) : "f"(__uint_as_float(src)))

// -------------------- prepass: transpose + tf32-round W ---------------------
extern "C" __global__ void prep_wt(const float* __restrict__ W_in,
                                   const float* __restrict__ W_self)
{
    int idx = blockIdx.x * 256 + threadIdx.x;   // 0 .. 262143
    int which = idx >> 17;
    int rem = idx & 131071;
    int k = rem >> 8;        // 0..511 (coalesced reads over n)
    int n = rem & 255;
    const float* W = which ? W_self : W_in;
    float v = W[k * DOUT_ + n];
    asm("cvt.rna.tf32.f32 %0, %1;" : "=f"(v) : "f"(v));
    int c = k >> 5, kk = k & 31;
    int byte = n * 128 + kk * 4;
    int sw = byte ^ ((byte >> 3) & 0x70);
    *(float*)((char*)&WT_sw[which][c][0][0] + sw) = v;
}

// ------------------------------- main kernel --------------------------------
extern "C" __global__ void __launch_bounds__(256, 1)
gcn_hmma(const float* __restrict__ rep,
         const float* __restrict__ adj_mask_in,
         const float* __restrict__ adj_mask_loop,
         const float* __restrict__ mask,
         const float* __restrict__ b_in,
         const float* __restrict__ bg_in,
         const float* __restrict__ Wg_in,
         const float* __restrict__ Wg_self,
         const int* __restrict__ arc,
         const int* __restrict__ lab,
         float* __restrict__ out)
{
    extern __shared__ char smem[];
    const u32 sb = smem_u32(smem);
    const int tid = threadIdx.x;
    const int ln = tid & 31;
    const int wid = tid >> 5;
    const int wm = wid >> 2;     // 0..1  (M half: 64 rows)
    const int wn = wid & 3;      // 0..3  (N quarter of 128: 32 cols)
    const int g = ln >> 2;
    const int t = ln & 3;
    const int m0 = blockIdx.x * 128;

    // ldmatrix lane-address components
    const int rowA = wm * 64 + (ln & 7) + ((ln >> 3) & 1) * 8;   // + mt*16
    const int koffA = ((ln >> 4) & 1) * 16;
    const int rowB = wn * 32 + ((ln >> 4) & 1) * 8 + (ln & 7);   // + nt2*16
    const int koffB = ((ln >> 3) & 1) * 16;

    // precomputed cp.async A-destination (swizzled) offsets: 1024 float4
    int arow[4], asw[4], aq[4];
#pragma unroll
    for (int i = 0; i < 4; i++) {
        int idx = tid + 256 * i;
        arow[i] = idx >> 3;
        aq[i] = idx & 7;
        int b = arow[i] * 128 + aq[i] * 16;
        asw[i] = b ^ ((b >> 3) & 0x70);
    }

    // ch = global chunk 0..31; phase = ch>>4 selects N-half; kc = ch&15
#define LOAD_CHUNK(ch)                                                         \
    do {                                                                       \
        int kc_ = (ch) & 15, p_ = (ch) >> 4;                                   \
        u32 stg = sb + OFF_STG + ((ch) % 3) * STG_STRIDE;                      \
        const char* ab = (const char*)rep + (size_t)m0 * 2048 + kc_ * 128;     \
        _Pragma("unroll")                                                      \
        for (int i = 0; i < 4; i++)                                            \
            cpa16(stg + asw[i], ab + (size_t)arow[i] * 2048 + aq[i] * 16);     \
        const char* bi = (const char*)WT_sw + (size_t)kc_ * 32768              \
                       + p_ * 16384;                                           \
        const char* bs = bi + (size_t)NCHUNK * 32768;                          \
        _Pragma("unroll")                                                      \
        for (int i = 0; i < 4; i++) {                                          \
            int o = (tid + 256 * i) * 16;                                      \
            cpa16(stg + 16384 + o, bi + o);                                    \
            cpa16(stg + 32768 + o, bs + o);                                    \
        }                                                                      \
        asm volatile("cp.async.commit_group;\n" ::: "memory");                 \
    } while (0)

    // prologue: chunks 0,1
    LOAD_CHUNK(0);
    LOAD_CHUNK(1);

    // ---------------- gate GEMVs (full fp32), overlap prologue --------------
    {
        int row = tid >> 1, half = tid & 1;  // 128 rows x 2 K-halves
        const float4* rp = (const float4*)(rep + (size_t)(m0 + row) * DIN_ + half * 256);
        const float4* gi = (const float4*)(Wg_in + half * 256);
        const float4* gs = (const float4*)(Wg_self + half * 256);
        float ai = 0.f, as = 0.f;
#pragma unroll 8
        for (int q = 0; q < 64; q++) {
            float4 v = rp[q], wi = gi[q], ws = gs[q];
            ai += v.x * wi.x + v.y * wi.y + v.z * wi.z + v.w * wi.w;
            as += v.x * ws.x + v.y * ws.y + v.z * ws.z + v.w * ws.w;
        }
        ai += __shfl_xor_sync(0xffffffffu, ai, 1);
        as += __shfl_xor_sync(0xffffffffu, as, 1);
        if (!half) {
            ((float*)(smem + OFF_GIN))[row] = ai;
            ((float*)(smem + OFF_GSF))[row] = as;
        }
    }

    float acc_in[4][4][4];   // [mt][nt(n8 within 32 cols)][quad]
    float acc_sf[4][4][4];
#pragma unroll
    for (int mt = 0; mt < 4; mt++)
#pragma unroll
        for (int nt = 0; nt < 4; nt++)
#pragma unroll
            for (int q = 0; q < 4; q++) { acc_in[mt][nt][q] = 0.f; acc_sf[mt][nt][q] = 0.f; }

    // ------------------------------ main loop -------------------------------
    // iter c: wait(group c), sync, issue load c+2, compute c.
#pragma unroll 1
    for (int c = 0; c < 32; c++) {
        if (c < 31)
            asm volatile("cp.async.wait_group 1;" ::: "memory");
        else
            asm volatile("cp.async.wait_group 0;" ::: "memory");
        __syncthreads();

        if (c < 30) LOAD_CHUNK(c + 2);

        const u32 stg = sb + OFF_STG + (c % 3) * STG_STRIDE;
        const u32 aBase = stg, biBase = stg + 16384, bsBase = stg + 32768;
#pragma unroll
        for (int ks = 0; ks < 4; ks++) {
            float a[4][4];
#pragma unroll
            for (int mt = 0; mt < 4; mt++) {
                int byte = (rowA + mt * 16) * 128 + ks * 32 + koffA;
                byte ^= (byte >> 3) & 0x70;
                u32 x0, x1, x2, x3;
                LDMX4(x0, x1, x2, x3, aBase + byte);
                CVT_TF32(a[mt][0], x0);
                CVT_TF32(a[mt][1], x1);
                CVT_TF32(a[mt][2], x2);
                CVT_TF32(a[mt][3], x3);
            }
#pragma unroll
            for (int nt2 = 0; nt2 < 2; nt2++) {
                int byte = (rowB + nt2 * 16) * 128 + ks * 32 + koffB;
                byte ^= (byte >> 3) & 0x70;
                u32 b0, b1, b2, b3;
                LDMX4(b0, b1, b2, b3, biBase + byte);
                u32 e0, e1, e2, e3;
                LDMX4(e0, e1, e2, e3, bsBase + byte);
#pragma unroll
                for (int mt = 0; mt < 4; mt++) {
                    MMA8(acc_in[mt][2 * nt2],     a[mt], b0, b1);
                    MMA8(acc_sf[mt][2 * nt2],     a[mt], e0, e1);
                    MMA8(acc_in[mt][2 * nt2 + 1], a[mt], b2, b3);
                    MMA8(acc_sf[mt][2 * nt2 + 1], a[mt], e2, e3);
                }
            }
        }

        // ---------------- per-phase epilogue at c == 15 / 31 -----------------
        if ((c & 15) == 15) {
            const int p = c >> 4;
            const int cbase = p * 128;
            // stash P_in half-tile (128 x 128) to swizzled SMEM (own cells)
#pragma unroll
            for (int mt = 0; mt < 4; mt++)
#pragma unroll
                for (int nt = 0; nt < 4; nt++)
#pragma unroll
                    for (int h = 0; h < 2; h++) {
                        int r = wm * 64 + mt * 16 + g + h * 8;
                        int cc4 = (wn * 32 + nt * 8 + 2 * t) * 4;
                        u32 ad = sb + OFF_PIN + r * 512 + (cc4 ^ ((r & 7) << 4));
                        asm volatile("st.shared.v2.f32 [%0], {%1,%2};"
                                     :: "r"(ad), "f"(acc_in[mt][nt][2 * h]),
                                        "f"(acc_in[mt][nt][2 * h + 1]) : "memory");
                    }
            if (p == 0 && tid < 128) {   // per-row params, once
                int r = tid, m = m0 + r;
                int lr = lab[m];
                int gl = (arc[2 * m] * L_ + arc[2 * m + 1]) - m0;
                gl &= 127;
                float mi = adj_mask_in[m], mlp = adj_mask_loop[m];
                float giv = ((float*)(smem + OFF_GIN))[gl] + bg_in[lr];
                float gsv = ((float*)(smem + OFF_GSF))[r];
                ((float*)(smem + OFF_WIN))[r] = (1.f / (1.f + expf(-giv))) * mi * mi;
                ((float*)(smem + OFF_WSF))[r] = (1.f / (1.f + expf(-gsv))) * mlp * mlp;
                ((float*)(smem + OFF_MKV))[r] = mask[m];
                ((int*)(smem + OFF_GLI))[r] = gl;
                ((int*)(smem + OFF_LRI))[r] = lr;
            }
            __syncthreads();

            // combine: gather + gates + relu + store for this column half
#pragma unroll
            for (int mt = 0; mt < 4; mt++)
#pragma unroll
                for (int h = 0; h < 2; h++) {
                    int r = wm * 64 + mt * 16 + g + h * 8;
                    float w_in = ((float*)(smem + OFF_WIN))[r];
                    float w_sf = ((float*)(smem + OFF_WSF))[r];
                    float mkr = ((float*)(smem + OFF_MKV))[r];
                    int gl = ((int*)(smem + OFF_GLI))[r];
                    int lr = ((int*)(smem + OFF_LRI))[r];
                    const u32 pinrow = sb + OFF_PIN + gl * 512;
                    const int xr = (gl & 7) << 4;
                    const float* bb = b_in + lr * DOUT_ + cbase;
                    float* op = out + (size_t)(m0 + r) * DOUT_ + cbase;
#pragma unroll
                    for (int nt = 0; nt < 4; nt++) {
                        int cc = wn * 32 + nt * 8 + 2 * t;
                        float px, py;
                        asm volatile("ld.shared.v2.f32 {%0,%1}, [%2];"
                                     : "=f"(px), "=f"(py)
                                     : "r"(pinrow + ((cc * 4) ^ xr)));
                        float2 bv = *(const float2*)(bb + cc);
                        float2 o;
                        o.x = fmaxf((px + bv.x) * w_in + acc_sf[mt][nt][2 * h] * w_sf, 0.f) * mkr;
                        o.y = fmaxf((py + bv.y) * w_in + acc_sf[mt][nt][2 * h + 1] * w_sf, 0.f) * mkr;
                        *(float2*)(op + cc) = o;
                    }
                }

            if (p == 0) {  // reset accumulators for second half
#pragma unroll
                for (int mt = 0; mt < 4; mt++)
#pragma unroll
                    for (int nt = 0; nt < 4; nt++)
#pragma unroll
                        for (int q = 0; q < 4; q++) {
                            acc_in[mt][nt][q] = 0.f;
                            acc_sf[mt][nt][q] = 0.f;
                        }
            }
        }
    }
}

extern "C" void kernel_launch(void* const* d_in, const int* in_sizes, int n_in,
                              void* d_out, int out_size)
{
    (void)in_sizes; (void)n_in; (void)out_size;
    cudaFuncSetAttribute(gcn_hmma, cudaFuncAttributeMaxDynamicSharedMemorySize,
                         SMEM_TOTAL);
    prep_wt<<<1024, 256>>>((const float*)d_in[4], (const float*)d_in[8]);
    gcn_hmma<<<BNK_ / 2, 256, SMEM_TOTAL>>>(
        (const float*)d_in[0],   // rep
        (const float*)d_in[1],   // adj_mask_in
        (const float*)d_in[2],   // adj_mask_loop
        (const float*)d_in[3],   // mask
        (const float*)d_in[5],   // b_in
        (const float*)d_in[7],   // b_gate_in
        (const float*)d_in[6],   // W_gate_in
        (const float*)d_in[9],   // W_gate_self
        (const int*)d_in[10],    // adj_arc_in
        (const int*)d_in[11],    // adj_lab_in
        (float*)d_out);
}

// round 13
// speedup vs baseline: 2.1855x; 1.0395x over previous
#include <cuda_runtime.h>
#include <cstdint>

// GCN layer via mma.sync tf32 (HMMA): N-half phases, merged dual-GEMM,
// 3-stage cp.async pipeline, one barrier per chunk.
// A operands: raw fp32 bits (HW tf32 truncation) — no cvt in mainloop.
// B operands: rna-rounded to tf32 in prepass.
// CTA = 128 rows (2 sentences), 256 threads, 8 warps (2M x 4N).
// Phase p (cols p*128..+127): warp tile 64x32 DUAL (P_in + P_self).

#define BNK_   1280
#define L_     64
#define DIN_   512
#define DOUT_  256
#define KC     32
#define NCHUNK 16

typedef unsigned int u32;

// Pre-transposed, tf32-rounded, SW128-swizzled W: [which][chunk][n=256][k=32]
__device__ float WT_sw[2][NCHUNK][DOUT_][KC];

// ---- SMEM byte offsets ----
#define OFF_GIN  0
#define OFF_GSF  512
#define OFF_WIN  1024
#define OFF_WSF  1536
#define OFF_MKV  2048
#define OFF_GLI  2560
#define OFF_LRI  3072
#define OFF_STG  4096
#define STG_STRIDE 49152          // A 16K + Bi 16K + Bs 16K
#define OFF_PIN  (OFF_STG + 3 * STG_STRIDE)    // 151552
#define SMEM_TOTAL (OFF_PIN + 65536)           // 217088

__device__ __forceinline__ u32 smem_u32(const void* p) {
    u32 a;
    asm("{ .reg .u64 t; cvta.to.shared.u64 t, %1; cvt.u32.u64 %0, t; }"
        : "=r"(a) : "l"(p));
    return a;
}
__device__ __forceinline__ void cpa16(u32 dst, const void* src) {
    asm volatile("cp.async.cg.shared.global [%0], [%1], 16;\n"
                 :: "r"(dst), "l"(src));
}

// A operands passed as raw u32 bits (tf32 = truncated fp32 in HW)
#define MMA8U(d, A, B0, B1)                                                   \
    asm volatile(                                                             \
        "mma.sync.aligned.m16n8k8.row.col.f32.tf32.tf32.f32 "                 \
        "{%0,%1,%2,%3}, {%4,%5,%6,%7}, {%8,%9}, {%0,%1,%2,%3};"               \
        : "+f"((d)[0]), "+f"((d)[1]), "+f"((d)[2]), "+f"((d)[3])              \
        : "r"((A)[0]), "r"((A)[1]), "r"((A)[2]), "r"((A)[3]),                 \
          "r"(B0), "r"(B1))

#define LDMX4(x0, x1, x2, x3, addr)                                           \
    asm volatile(                                                             \
        "ldmatrix.sync.aligned.m8n8.x4.shared.b16 {%0,%1,%2,%3}, [%4];"       \
        : "=r"(x0), "=r"(x1), "=r"(x2), "=r"(x3) : "r"(addr))

// -------------------- prepass: transpose + tf32-round W ---------------------
extern "C" __global__ void prep_wt(const float* __restrict__ W_in,
                                   const float* __restrict__ W_self)
{
    int idx = blockIdx.x * 256 + threadIdx.x;   // 0 .. 262143
    int which = idx >> 17;
    int rem = idx & 131071;
    int k = rem >> 8;        // 0..511 (coalesced reads over n)
    int n = rem & 255;
    const float* W = which ? W_self : W_in;
    float v = W[k * DOUT_ + n];
    asm("cvt.rna.tf32.f32 %0, %1;" : "=f"(v) : "f"(v));
    int c = k >> 5, kk = k & 31;
    int byte = n * 128 + kk * 4;
    int sw = byte ^ ((byte >> 3) & 0x70);
    *(float*)((char*)&WT_sw[which][c][0][0] + sw) = v;
}

// ------------------------------- main kernel --------------------------------
extern "C" __global__ void __launch_bounds__(256, 1)
gcn_hmma(const float* __restrict__ rep,
         const float* __restrict__ adj_mask_in,
         const float* __restrict__ adj_mask_loop,
         const float* __restrict__ mask,
         const float* __restrict__ b_in,
         const float* __restrict__ bg_in,
         const float* __restrict__ Wg_in,
         const float* __restrict__ Wg_self,
         const int* __restrict__ arc,
         const int* __restrict__ lab,
         float* __restrict__ out)
{
    extern __shared__ char smem[];
    const u32 sb = smem_u32(smem);
    const int tid = threadIdx.x;
    const int ln = tid & 31;
    const int wid = tid >> 5;
    const int wm = wid >> 2;     // 0..1  (M half: 64 rows)
    const int wn = wid & 3;      // 0..3  (N quarter of 128: 32 cols)
    const int g = ln >> 2;
    const int t = ln & 3;
    const int m0 = blockIdx.x * 128;

    // ldmatrix lane-address components
    const int rowA = wm * 64 + (ln & 7) + ((ln >> 3) & 1) * 8;   // + mt*16
    const int koffA = ((ln >> 4) & 1) * 16;
    const int rowB = wn * 32 + ((ln >> 4) & 1) * 8 + (ln & 7);   // + nt2*16
    const int koffB = ((ln >> 3) & 1) * 16;

    // precomputed cp.async A-destination (swizzled) offsets: 1024 float4
    int arow[4], asw[4], aq[4];
#pragma unroll
    for (int i = 0; i < 4; i++) {
        int idx = tid + 256 * i;
        arow[i] = idx >> 3;
        aq[i] = idx & 7;
        int b = arow[i] * 128 + aq[i] * 16;
        asw[i] = b ^ ((b >> 3) & 0x70);
    }

    // ch = global chunk 0..31; phase = ch>>4 selects N-half; kc = ch&15
#define LOAD_CHUNK(ch)                                                         \
    do {                                                                       \
        int kc_ = (ch) & 15, p_ = (ch) >> 4;                                   \
        u32 stg = sb + OFF_STG + ((ch) % 3) * STG_STRIDE;                      \
        const char* ab = (const char*)rep + (size_t)m0 * 2048 + kc_ * 128;     \
        _Pragma("unroll")                                                      \
        for (int i = 0; i < 4; i++)                                            \
            cpa16(stg + asw[i], ab + (size_t)arow[i] * 2048 + aq[i] * 16);     \
        const char* bi = (const char*)WT_sw + (size_t)kc_ * 32768              \
                       + p_ * 16384;                                           \
        const char* bs = bi + (size_t)NCHUNK * 32768;                          \
        _Pragma("unroll")                                                      \
        for (int i = 0; i < 4; i++) {                                          \
            int o = (tid + 256 * i) * 16;                                      \
            cpa16(stg + 16384 + o, bi + o);                                    \
            cpa16(stg + 32768 + o, bs + o);                                    \
        }                                                                      \
        asm volatile("cp.async.commit_group;\n" ::: "memory");                 \
    } while (0)

    // prologue: chunks 0,1
    LOAD_CHUNK(0);
    LOAD_CHUNK(1);

    // ---------------- gate GEMVs (full fp32), overlap prologue --------------
    {
        int row = tid >> 1, half = tid & 1;  // 128 rows x 2 K-halves
        const float4* rp = (const float4*)(rep + (size_t)(m0 + row) * DIN_ + half * 256);
        const float4* gi = (const float4*)(Wg_in + half * 256);
        const float4* gs = (const float4*)(Wg_self + half * 256);
        float ai = 0.f, as = 0.f;
#pragma unroll 8
        for (int q = 0; q < 64; q++) {
            float4 v = rp[q], wi = gi[q], ws = gs[q];
            ai += v.x * wi.x + v.y * wi.y + v.z * wi.z + v.w * wi.w;
            as += v.x * ws.x + v.y * ws.y + v.z * ws.z + v.w * ws.w;
        }
        ai += __shfl_xor_sync(0xffffffffu, ai, 1);
        as += __shfl_xor_sync(0xffffffffu, as, 1);
        if (!half) {
            ((float*)(smem + OFF_GIN))[row] = ai;
            ((float*)(smem + OFF_GSF))[row] = as;
        }
    }

    float acc_in[4][4][4];   // [mt][nt(n8 within 32 cols)][quad]
    float acc_sf[4][4][4];
#pragma unroll
    for (int mt = 0; mt < 4; mt++)
#pragma unroll
        for (int nt = 0; nt < 4; nt++)
#pragma unroll
            for (int q = 0; q < 4; q++) { acc_in[mt][nt][q] = 0.f; acc_sf[mt][nt][q] = 0.f; }

    // ------------------------------ main loop -------------------------------
    // iter c: wait(group c), sync, issue load c+2, compute c.
#pragma unroll 1
    for (int c = 0; c < 32; c++) {
        if (c < 31)
            asm volatile("cp.async.wait_group 1;" ::: "memory");
        else
            asm volatile("cp.async.wait_group 0;" ::: "memory");
        __syncthreads();

        if (c < 30) LOAD_CHUNK(c + 2);

        const u32 stg = sb + OFF_STG + (c % 3) * STG_STRIDE;
        const u32 aBase = stg, biBase = stg + 16384, bsBase = stg + 32768;
#pragma unroll
        for (int ks = 0; ks < 4; ks++) {
            u32 a[4][4];   // raw fp32 bits -> HW tf32 truncation
#pragma unroll
            for (int mt = 0; mt < 4; mt++) {
                int byte = (rowA + mt * 16) * 128 + ks * 32 + koffA;
                byte ^= (byte >> 3) & 0x70;
                LDMX4(a[mt][0], a[mt][1], a[mt][2], a[mt][3], aBase + byte);
            }
#pragma unroll
            for (int nt2 = 0; nt2 < 2; nt2++) {
                int byte = (rowB + nt2 * 16) * 128 + ks * 32 + koffB;
                byte ^= (byte >> 3) & 0x70;
                u32 b0, b1, b2, b3;
                LDMX4(b0, b1, b2, b3, biBase + byte);
                u32 e0, e1, e2, e3;
                LDMX4(e0, e1, e2, e3, bsBase + byte);
#pragma unroll
                for (int mt = 0; mt < 4; mt++) {
                    MMA8U(acc_in[mt][2 * nt2],     a[mt], b0, b1);
                    MMA8U(acc_sf[mt][2 * nt2],     a[mt], e0, e1);
                    MMA8U(acc_in[mt][2 * nt2 + 1], a[mt], b2, b3);
                    MMA8U(acc_sf[mt][2 * nt2 + 1], a[mt], e2, e3);
                }
            }
        }

        // ---------------- per-phase epilogue at c == 15 / 31 -----------------
        if ((c & 15) == 15) {
            const int p = c >> 4;
            const int cbase = p * 128;
            // stash P_in half-tile (128 x 128) to swizzled SMEM (own cells)
#pragma unroll
            for (int mt = 0; mt < 4; mt++)
#pragma unroll
                for (int nt = 0; nt < 4; nt++)
#pragma unroll
                    for (int h = 0; h < 2; h++) {
                        int r = wm * 64 + mt * 16 + g + h * 8;
                        int cc4 = (wn * 32 + nt * 8 + 2 * t) * 4;
                        u32 ad = sb + OFF_PIN + r * 512 + (cc4 ^ ((r & 7) << 4));
                        asm volatile("st.shared.v2.f32 [%0], {%1,%2};"
                                     :: "r"(ad), "f"(acc_in[mt][nt][2 * h]),
                                        "f"(acc_in[mt][nt][2 * h + 1]) : "memory");
                    }
            if (p == 0 && tid < 128) {   // per-row params, once
                int r = tid, m = m0 + r;
                int lr = lab[m];
                int gl = (arc[2 * m] * L_ + arc[2 * m + 1]) - m0;
                gl &= 127;
                float mi = adj_mask_in[m], mlp = adj_mask_loop[m];
                float giv = ((float*)(smem + OFF_GIN))[gl] + bg_in[lr];
                float gsv = ((float*)(smem + OFF_GSF))[r];
                ((float*)(smem + OFF_WIN))[r] = (1.f / (1.f + expf(-giv))) * mi * mi;
                ((float*)(smem + OFF_WSF))[r] = (1.f / (1.f + expf(-gsv))) * mlp * mlp;
                ((float*)(smem + OFF_MKV))[r] = mask[m];
                ((int*)(smem + OFF_GLI))[r] = gl;
                ((int*)(smem + OFF_LRI))[r] = lr;
            }
            __syncthreads();

            // combine: gather + gates + relu + store for this column half
#pragma unroll
            for (int mt = 0; mt < 4; mt++)
#pragma unroll
                for (int h = 0; h < 2; h++) {
                    int r = wm * 64 + mt * 16 + g + h * 8;
                    float w_in = ((float*)(smem + OFF_WIN))[r];
                    float w_sf = ((float*)(smem + OFF_WSF))[r];
                    float mkr = ((float*)(smem + OFF_MKV))[r];
                    int gl = ((int*)(smem + OFF_GLI))[r];
                    int lr = ((int*)(smem + OFF_LRI))[r];
                    const u32 pinrow = sb + OFF_PIN + gl * 512;
                    const int xr = (gl & 7) << 4;
                    const float* bb = b_in + lr * DOUT_ + cbase;
                    float* op = out + (size_t)(m0 + r) * DOUT_ + cbase;
#pragma unroll
                    for (int nt = 0; nt < 4; nt++) {
                        int cc = wn * 32 + nt * 8 + 2 * t;
                        float px, py;
                        asm volatile("ld.shared.v2.f32 {%0,%1}, [%2];"
                                     : "=f"(px), "=f"(py)
                                     : "r"(pinrow + ((cc * 4) ^ xr)));
                        float2 bv = *(const float2*)(bb + cc);
                        float2 o;
                        o.x = fmaxf((px + bv.x) * w_in + acc_sf[mt][nt][2 * h] * w_sf, 0.f) * mkr;
                        o.y = fmaxf((py + bv.y) * w_in + acc_sf[mt][nt][2 * h + 1] * w_sf, 0.f) * mkr;
                        *(float2*)(op + cc) = o;
                    }
                }

            if (p == 0) {  // reset accumulators for second half
#pragma unroll
                for (int mt = 0; mt < 4; mt++)
#pragma unroll
                    for (int nt = 0; nt < 4; nt++)
#pragma unroll
                        for (int q = 0; q < 4; q++) {
                            acc_in[mt][nt][q] = 0.f;
                            acc_sf[mt][nt][q] = 0.f;
                        }
            }
        }
    }
}

extern "C" void kernel_launch(void* const* d_in, const int* in_sizes, int n_in,
                              void* d_out, int out_size)
{
    (void)in_sizes; (void)n_in; (void)out_size;
    cudaFuncSetAttribute(gcn_hmma, cudaFuncAttributeMaxDynamicSharedMemorySize,
                         SMEM_TOTAL);
    prep_wt<<<1024, 256>>>((const float*)d_in[4], (const float*)d_in[8]);
    gcn_hmma<<<BNK_ / 2, 256, SMEM_TOTAL>>>(
        (const float*)d_in[0],   // rep
        (const float*)d_in[1],   // adj_mask_in
        (const float*)d_in[2],   // adj_mask_loop
        (const float*)d_in[3],   // mask
        (const float*)d_in[5],   // b_in
        (const float*)d_in[7],   // b_gate_in
        (const float*)d_in[6],   // W_gate_in
        (const float*)d_in[9],   // W_gate_self
        (const int*)d_in[10],    // adj_arc_in
        (const int*)d_in[11],    // adj_lab_in
        (float*)d_out);
}